// round 3
// baseline (speedup 1.0000x reference)
#include <cuda_runtime.h>
#include <cstdint>

#define HDIM   1024
#define BATCH  16384
#define BHTOT  (BATCH * HDIM)

#define BM 128
#define BN 256
#define BK 32
#define KTILES (HDIM / BK)
#define NSTAGE 3
#define PAF 36                        // floats per smem row (pitch), conflict-free
#define A_STG_FLOATS (BM * PAF)       // 4608
#define B_STG_FLOATS (BN * PAF)       // 9216
#define STG_FLOATS   (A_STG_FLOATS + B_STG_FLOATS)   // 13824
#define GEMM_SMEM    (NSTAGE * STG_FLOATS * 4)       // 165888 bytes

// ---------------- scratch (device globals; no allocation) ----------------
__device__ float4 g_xk[BHTOT / 4];
__device__ float4 g_xv[BHTOT / 4];
__device__ float4 g_xr[BHTOT / 4];
__device__ float4 g_k [BHTOT / 4];
__device__ float4 g_v [BHTOT / 4];
__device__ float4 g_r [BHTOT / 4];
__device__ float4 g_wk[HDIM * HDIM / 4];
__device__ float4 g_wv[HDIM * HDIM / 4];
__device__ float4 g_wr[HDIM * HDIM / 4];
__device__ float4 g_wo[HDIM * HDIM / 4];

// ---------------- helpers ----------------
__device__ __forceinline__ uint32_t smem_u32(const void* p) {
    uint32_t a;
    asm("{ .reg .u64 t; cvta.to.shared.u64 t, %1; cvt.u32.u64 %0, t; }" : "=r"(a) : "l"(p));
    return a;
}
__device__ __forceinline__ float tf32r(float f) {
    uint32_t u;
    asm("cvt.rna.tf32.f32 %0, %1;" : "=r"(u) : "f"(f));
    return __uint_as_float(u);
}
#define CP_ASYNC16(sa, ga) \
    asm volatile("cp.async.cg.shared.global [%0], [%1], 16;" :: "r"(sa), "l"(ga))
#define CP_COMMIT()  asm volatile("cp.async.commit_group;" ::: "memory")
#define CP_WAIT(n)   asm volatile("cp.async.wait_group %0;" :: "n"(n) : "memory")
#define CP_WAIT_ALL() asm volatile("cp.async.wait_all;" ::: "memory")

__device__ __forceinline__ void mma_tf32(float& d0, float& d1, float& d2, float& d3,
                                         uint32_t a0, uint32_t a1, uint32_t a2, uint32_t a3,
                                         uint32_t b0, uint32_t b1) {
    asm volatile(
        "mma.sync.aligned.m16n8k8.row.col.f32.tf32.tf32.f32 "
        "{%0,%1,%2,%3},{%4,%5,%6,%7},{%8,%9},{%0,%1,%2,%3};"
        : "+f"(d0), "+f"(d1), "+f"(d2), "+f"(d3)
        : "r"(a0), "r"(a1), "r"(a2), "r"(a3), "r"(b0), "r"(b1));
}

// ---------------- kernel: weight tf32 rounding ----------------
__global__ void wconv_kernel(const float4* __restrict__ w0, const float4* __restrict__ w1,
                             const float4* __restrict__ w2, const float4* __restrict__ w3) {
    int i = blockIdx.x * 256 + threadIdx.x;
    int y = blockIdx.y;
    const float4* s = (y == 0) ? w0 : (y == 1) ? w1 : (y == 2) ? w2 : w3;
    float4* d = (y == 0) ? g_wk : (y == 1) ? g_wv : (y == 2) ? g_wr : g_wo;
    float4 v = s[i];
    v.x = tf32r(v.x); v.y = tf32r(v.y); v.z = tf32r(v.z); v.w = tf32r(v.w);
    d[i] = v;
}

// ---------------- kernel: premix + x passthrough ----------------
__device__ __forceinline__ float mixf(float x, float a, float m) {
    return tf32r(fmaf(x - a, m, a));
}
__global__ void premix_kernel(const float4* __restrict__ x, const float4* __restrict__ al,
                              const float4* __restrict__ tmk, const float4* __restrict__ tmv,
                              const float4* __restrict__ tmr, float4* __restrict__ outx) {
    int i = blockIdx.x * 256 + threadIdx.x;
    int c = i & (HDIM / 4 - 1);
    float4 xv = x[i], av = al[i];
    float4 mk = tmk[c], mv = tmv[c], mr = tmr[c];
    float4 ok, ov, orr;
    ok.x  = mixf(xv.x, av.x, mk.x); ok.y  = mixf(xv.y, av.y, mk.y);
    ok.z  = mixf(xv.z, av.z, mk.z); ok.w  = mixf(xv.w, av.w, mk.w);
    ov.x  = mixf(xv.x, av.x, mv.x); ov.y  = mixf(xv.y, av.y, mv.y);
    ov.z  = mixf(xv.z, av.z, mv.z); ov.w  = mixf(xv.w, av.w, mv.w);
    orr.x = mixf(xv.x, av.x, mr.x); orr.y = mixf(xv.y, av.y, mr.y);
    orr.z = mixf(xv.z, av.z, mr.z); orr.w = mixf(xv.w, av.w, mr.w);
    g_xk[i] = ok; g_xv[i] = ov; g_xr[i] = orr;
    outx[i] = xv;
}

// ---------------- GEMM: D[16384,1024] = A @ W^T (tf32 mma.sync) ----------------
// A row-major [B,H]; W row-major [H,H] (rows = output features). mode1: sigmoid.
__global__ void __launch_bounds__(256, 1)
gemm_kernel(const float* __restrict__ A, const float* __restrict__ W,
            float* __restrict__ D, int mode) {
    extern __shared__ __align__(128) float smem[];
    const int tid = threadIdx.x;
    const int lane = tid & 31, wid = tid >> 5;
    const int gid = lane >> 2, t4 = lane & 3;
    const int warpM = (wid >> 2) * 64;        // 0 or 64
    const int warpN = (wid & 3) * 64;         // 0,64,128,192
    const int mtB = (int)(blockIdx.x >> 2) * BM;
    const int ntB = (int)(blockIdx.x & 3) * BN;

    const float* Ab = A + (size_t)mtB * HDIM;
    const float* Wb = W + (size_t)ntB * HDIM;
    const uint32_t sbase = smem_u32(smem);

    // stage loader: A 128x32, B 256x32, pitch 36 floats
    auto load_stage = [&](int stage, int kt) {
        const uint32_t sA = sbase + stage * (STG_FLOATS * 4);
        const uint32_t sB = sA + A_STG_FLOATS * 4;
        const float* ga = Ab + kt * BK;
        const float* gb = Wb + kt * BK;
#pragma unroll
        for (int i = 0; i < 4; i++) {          // A: 1024 chunks
            int q = tid + 256 * i;
            int row = q >> 3, c = q & 7;
            CP_ASYNC16(sA + (row * PAF + c * 4) * 4, ga + (size_t)row * HDIM + c * 4);
        }
#pragma unroll
        for (int i = 0; i < 8; i++) {          // B: 2048 chunks
            int q = tid + 256 * i;
            int row = q >> 3, c = q & 7;
            CP_ASYNC16(sB + (row * PAF + c * 4) * 4, gb + (size_t)row * HDIM + c * 4);
        }
        CP_COMMIT();
    };

    float acc[4][8][4];
#pragma unroll
    for (int mt = 0; mt < 4; mt++)
#pragma unroll
        for (int nt = 0; nt < 8; nt++)
#pragma unroll
            for (int e = 0; e < 4; e++) acc[mt][nt][e] = 0.0f;

    // prologue: stages 0..NSTAGE-2
#pragma unroll
    for (int p = 0; p < NSTAGE - 1; p++) load_stage(p, p);

    for (int kt = 0; kt < KTILES; kt++) {
        CP_WAIT(NSTAGE - 2);
        __syncthreads();
        const int L = kt + NSTAGE - 1;
        if (L < KTILES) load_stage(L % NSTAGE, L);

        const float* As = smem + (kt % NSTAGE) * STG_FLOATS;
        const float* Bs = As + A_STG_FLOATS;
#pragma unroll
        for (int ks = 0; ks < 4; ks++) {
            const int kb = ks * 8;
            uint32_t af[4][4], bf[8][2];
#pragma unroll
            for (int mt = 0; mt < 4; mt++) {
                const float* ap = As + (warpM + 16 * mt + gid) * PAF + kb + t4;
                af[mt][0] = __float_as_uint(ap[0]);
                af[mt][1] = __float_as_uint(ap[8 * PAF]);
                af[mt][2] = __float_as_uint(ap[4]);
                af[mt][3] = __float_as_uint(ap[8 * PAF + 4]);
            }
#pragma unroll
            for (int nt = 0; nt < 8; nt++) {
                const float* bp = Bs + (warpN + 8 * nt + gid) * PAF + kb + t4;
                bf[nt][0] = __float_as_uint(bp[0]);
                bf[nt][1] = __float_as_uint(bp[4]);
            }
#pragma unroll
            for (int mt = 0; mt < 4; mt++)
#pragma unroll
                for (int nt = 0; nt < 8; nt++)
                    mma_tf32(acc[mt][nt][0], acc[mt][nt][1], acc[mt][nt][2], acc[mt][nt][3],
                             af[mt][0], af[mt][1], af[mt][2], af[mt][3],
                             bf[nt][0], bf[nt][1]);
        }
        __syncthreads();
    }
    CP_WAIT_ALL();

    // epilogue
#pragma unroll
    for (int mt = 0; mt < 4; mt++) {
#pragma unroll
        for (int nt = 0; nt < 8; nt++) {
            float v0 = acc[mt][nt][0], v1 = acc[mt][nt][1];
            float v2 = acc[mt][nt][2], v3 = acc[mt][nt][3];
            if (mode == 1) {
                v0 = 1.0f / (1.0f + __expf(-v0));
                v1 = 1.0f / (1.0f + __expf(-v1));
                v2 = 1.0f / (1.0f + __expf(-v2));
                v3 = 1.0f / (1.0f + __expf(-v3));
            }
            int row = mtB + warpM + 16 * mt + gid;
            int col = ntB + warpN + 8 * nt + 2 * t4;
            float2* p0 = (float2*)(D + (size_t)row * HDIM + col);
            float2* p1 = (float2*)(D + (size_t)(row + 8) * HDIM + col);
            *p0 = make_float2(v0, v1);
            *p1 = make_float2(v2, v3);
        }
    }
}

// ---------------- kernel: WKV elementwise ----------------
__global__ void wkv_kernel(const float4* __restrict__ aa, const float4* __restrict__ bb,
                           const float4* __restrict__ pp, const float4* __restrict__ td,
                           const float4* __restrict__ tf, float4* __restrict__ out_aa,
                           float4* __restrict__ out_bb, float4* __restrict__ out_qq) {
    int i = blockIdx.x * 256 + threadIdx.x;
    int c = i & (HDIM / 4 - 1);
    float4 k4 = g_k[i], v4 = g_v[i], r4 = g_r[i];
    float4 a4 = aa[i], b4 = bb[i], p4 = pp[i];
    float4 tf4 = tf[c], td4 = td[c];
    float kk[4] = {k4.x, k4.y, k4.z, k4.w};
    float vv[4] = {v4.x, v4.y, v4.z, v4.w};
    float rr[4] = {r4.x, r4.y, r4.z, r4.w};
    float av[4] = {a4.x, a4.y, a4.z, a4.w};
    float bv[4] = {b4.x, b4.y, b4.z, b4.w};
    float pv[4] = {p4.x, p4.y, p4.z, p4.w};
    float tfv[4] = {tf4.x, tf4.y, tf4.z, tf4.w};
    float tdv[4] = {td4.x, td4.y, td4.z, td4.w};
    float o_rw[4], o_na[4], o_nb[4], o_q2[4];
#pragma unroll
    for (int j = 0; j < 4; j++) {
        float ww = tfv[j] + kk[j];
        float qq = fmaxf(pv[j], ww);
        float e1 = __expf(pv[j] - qq);
        float e2 = __expf(ww - qq);
        float wkv = (e1 * av[j] + e2 * vv[j]) / (e1 * bv[j] + e2);
        float ww2 = pv[j] + tdv[j];
        float qq2 = fmaxf(ww2, kk[j]);
        float e1b = __expf(ww2 - qq2);
        float e2b = __expf(kk[j] - qq2);
        o_na[j] = e1b * av[j] + e2b * vv[j];
        o_nb[j] = e1b * bv[j] + e2b;
        o_q2[j] = qq2;
        o_rw[j] = tf32r(rr[j] * wkv);
    }
    float4 rw = make_float4(o_rw[0], o_rw[1], o_rw[2], o_rw[3]);
    float4 na = make_float4(o_na[0], o_na[1], o_na[2], o_na[3]);
    float4 nb = make_float4(o_nb[0], o_nb[1], o_nb[2], o_nb[3]);
    float4 q2 = make_float4(o_q2[0], o_q2[1], o_q2[2], o_q2[3]);
    g_xk[i] = rw;      // reuse as O-GEMM input
    out_aa[i] = na;
    out_bb[i] = nb;
    out_qq[i] = q2;
}

// ---------------- launch ----------------
extern "C" void kernel_launch(void* const* d_in, const int* in_sizes, int n_in,
                              void* d_out, int out_size) {
    (void)in_sizes; (void)n_in; (void)out_size;
    const float4* x   = (const float4*)d_in[0];
    const float4* al  = (const float4*)d_in[1];
    const float4* aa  = (const float4*)d_in[2];
    const float4* bb  = (const float4*)d_in[3];
    const float4* pp  = (const float4*)d_in[4];
    const float4* td  = (const float4*)d_in[5];
    const float4* tf  = (const float4*)d_in[6];
    const float4* tmk = (const float4*)d_in[7];
    const float4* tmv = (const float4*)d_in[8];
    const float4* tmr = (const float4*)d_in[9];
    const float4* Wk  = (const float4*)d_in[10];
    const float4* Wv  = (const float4*)d_in[11];
    const float4* Wr  = (const float4*)d_in[12];
    const float4* Wo  = (const float4*)d_in[13];
    float* out = (float*)d_out;

    cudaFuncSetAttribute(gemm_kernel, cudaFuncAttributeMaxDynamicSharedMemorySize, GEMM_SMEM);

    float *p_xk, *p_xv, *p_xr, *p_k, *p_v, *p_r, *p_wk, *p_wv, *p_wr, *p_wo;
    cudaGetSymbolAddress((void**)&p_xk, g_xk);
    cudaGetSymbolAddress((void**)&p_xv, g_xv);
    cudaGetSymbolAddress((void**)&p_xr, g_xr);
    cudaGetSymbolAddress((void**)&p_k,  g_k);
    cudaGetSymbolAddress((void**)&p_v,  g_v);
    cudaGetSymbolAddress((void**)&p_r,  g_r);
    cudaGetSymbolAddress((void**)&p_wk, g_wk);
    cudaGetSymbolAddress((void**)&p_wv, g_wv);
    cudaGetSymbolAddress((void**)&p_wr, g_wr);
    cudaGetSymbolAddress((void**)&p_wo, g_wo);

    wconv_kernel<<<dim3(HDIM * HDIM / 4 / 256, 4), 256>>>(Wk, Wv, Wr, Wo);
    premix_kernel<<<BHTOT / 4 / 256, 256>>>(x, al, tmk, tmv, tmr,
                                            (float4*)(out + (size_t)BHTOT));
    gemm_kernel<<<512, 256, GEMM_SMEM>>>(p_xk, p_wk, p_k, 0);
    gemm_kernel<<<512, 256, GEMM_SMEM>>>(p_xv, p_wv, p_v, 0);
    gemm_kernel<<<512, 256, GEMM_SMEM>>>(p_xr, p_wr, p_r, 1);
    wkv_kernel<<<BHTOT / 4 / 256, 256>>>(aa, bb, pp, td, tf,
                                         (float4*)(out + 2 * (size_t)BHTOT),
                                         (float4*)(out + 3 * (size_t)BHTOT),
                                         (float4*)(out + 4 * (size_t)BHTOT));
    gemm_kernel<<<512, 256, GEMM_SMEM>>>(p_xk, p_wo, out, 0);
}

// round 4
// speedup vs baseline: 1.1193x; 1.1193x over previous
#include <cuda_runtime.h>
#include <cstdint>

#define HDIM   1024
#define BATCH  16384
#define BHTOT  (BATCH * HDIM)

#define BM 128
#define BN 128
#define BK 32
#define KTILES (HDIM / BK)
#define NSTAGE 3
#define PAF 36                        // floats per smem row (pitch), conflict-free
#define A_STG_FLOATS (BM * PAF)       // 4608
#define B_STG_FLOATS (BN * PAF)       // 4608
#define STG_FLOATS   (A_STG_FLOATS + B_STG_FLOATS)   // 9216
#define GEMM_SMEM    (NSTAGE * STG_FLOATS * 4)       // 110592 bytes

// ---------------- scratch (device globals; no allocation) ----------------
__device__ float4 g_xk[BHTOT / 4];
__device__ float4 g_xv[BHTOT / 4];
__device__ float4 g_xr[BHTOT / 4];
__device__ float4 g_k [BHTOT / 4];
__device__ float4 g_v [BHTOT / 4];
__device__ float4 g_r [BHTOT / 4];
__device__ float4 g_wk[HDIM * HDIM / 4];
__device__ float4 g_wv[HDIM * HDIM / 4];
__device__ float4 g_wr[HDIM * HDIM / 4];
__device__ float4 g_wo[HDIM * HDIM / 4];

// ---------------- helpers ----------------
__device__ __forceinline__ uint32_t smem_u32(const void* p) {
    uint32_t a;
    asm("{ .reg .u64 t; cvta.to.shared.u64 t, %1; cvt.u32.u64 %0, t; }" : "=r"(a) : "l"(p));
    return a;
}
__device__ __forceinline__ float tf32r(float f) {
    uint32_t u;
    asm("cvt.rna.tf32.f32 %0, %1;" : "=r"(u) : "f"(f));
    return __uint_as_float(u);
}
#define CP_ASYNC16(sa, ga) \
    asm volatile("cp.async.cg.shared.global [%0], [%1], 16;" :: "r"(sa), "l"(ga))
#define CP_COMMIT()  asm volatile("cp.async.commit_group;" ::: "memory")
#define CP_WAIT(n)   asm volatile("cp.async.wait_group %0;" :: "n"(n) : "memory")
#define CP_WAIT_ALL() asm volatile("cp.async.wait_all;" ::: "memory")

__device__ __forceinline__ void mma_tf32(float& d0, float& d1, float& d2, float& d3,
                                         uint32_t a0, uint32_t a1, uint32_t a2, uint32_t a3,
                                         uint32_t b0, uint32_t b1) {
    asm volatile(
        "mma.sync.aligned.m16n8k8.row.col.f32.tf32.tf32.f32 "
        "{%0,%1,%2,%3},{%4,%5,%6,%7},{%8,%9},{%0,%1,%2,%3};"
        : "+f"(d0), "+f"(d1), "+f"(d2), "+f"(d3)
        : "r"(a0), "r"(a1), "r"(a2), "r"(a3), "r"(b0), "r"(b1));
}

// ---------------- kernel: weight tf32 rounding ----------------
__global__ void wconv_kernel(const float4* __restrict__ w0, const float4* __restrict__ w1,
                             const float4* __restrict__ w2, const float4* __restrict__ w3) {
    int i = blockIdx.x * 256 + threadIdx.x;
    int y = blockIdx.y;
    const float4* s = (y == 0) ? w0 : (y == 1) ? w1 : (y == 2) ? w2 : w3;
    float4* d = (y == 0) ? g_wk : (y == 1) ? g_wv : (y == 2) ? g_wr : g_wo;
    float4 v = s[i];
    v.x = tf32r(v.x); v.y = tf32r(v.y); v.z = tf32r(v.z); v.w = tf32r(v.w);
    d[i] = v;
}

// ---------------- kernel: premix + x passthrough ----------------
__device__ __forceinline__ float mixf(float x, float a, float m) {
    return tf32r(fmaf(x - a, m, a));
}
__global__ void premix_kernel(const float4* __restrict__ x, const float4* __restrict__ al,
                              const float4* __restrict__ tmk, const float4* __restrict__ tmv,
                              const float4* __restrict__ tmr, float4* __restrict__ outx) {
    int i = blockIdx.x * 256 + threadIdx.x;
    int c = i & (HDIM / 4 - 1);
    float4 xv = x[i], av = al[i];
    float4 mk = tmk[c], mv = tmv[c], mr = tmr[c];
    float4 ok, ov, orr;
    ok.x  = mixf(xv.x, av.x, mk.x); ok.y  = mixf(xv.y, av.y, mk.y);
    ok.z  = mixf(xv.z, av.z, mk.z); ok.w  = mixf(xv.w, av.w, mk.w);
    ov.x  = mixf(xv.x, av.x, mv.x); ov.y  = mixf(xv.y, av.y, mv.y);
    ov.z  = mixf(xv.z, av.z, mv.z); ov.w  = mixf(xv.w, av.w, mv.w);
    orr.x = mixf(xv.x, av.x, mr.x); orr.y = mixf(xv.y, av.y, mr.y);
    orr.z = mixf(xv.z, av.z, mr.z); orr.w = mixf(xv.w, av.w, mr.w);
    g_xk[i] = ok; g_xv[i] = ov; g_xr[i] = orr;
    outx[i] = xv;
}

// ---------------- GEMM: D[16384,1024] = A @ W^T (tf32 mma.sync) ----------------
// A row-major [B,H]; W row-major [H,H] (rows = output features). mode1: sigmoid.
// 2 CTAs/SM: BMxBN = 128x128, 8 warps, warp tile 64x32.
__global__ void __launch_bounds__(256, 2)
gemm_kernel(const float* __restrict__ A, const float* __restrict__ W,
            float* __restrict__ D, int mode) {
    extern __shared__ __align__(128) float smem[];
    const int tid = threadIdx.x;
    const int lane = tid & 31, wid = tid >> 5;
    const int gid = lane >> 2, t4 = lane & 3;
    const int warpM = (wid >> 2) * 64;        // 0 or 64
    const int warpN = (wid & 3) * 32;         // 0,32,64,96
    const int mtB = (int)(blockIdx.x >> 3) * BM;
    const int ntB = (int)(blockIdx.x & 7) * BN;

    const float* Ab = A + (size_t)mtB * HDIM;
    const float* Wb = W + (size_t)ntB * HDIM;
    const uint32_t sbase = smem_u32(smem);

    // stage loader: A 128x32, B 128x32, pitch 36 floats
    auto load_stage = [&](int stage, int kt) {
        const uint32_t sA = sbase + stage * (STG_FLOATS * 4);
        const uint32_t sB = sA + A_STG_FLOATS * 4;
        const float* ga = Ab + kt * BK;
        const float* gb = Wb + kt * BK;
#pragma unroll
        for (int i = 0; i < 4; i++) {          // A: 1024 16B-chunks
            int q = tid + 256 * i;
            int row = q >> 3, c = q & 7;
            CP_ASYNC16(sA + (row * PAF + c * 4) * 4, ga + (size_t)row * HDIM + c * 4);
        }
#pragma unroll
        for (int i = 0; i < 4; i++) {          // B: 1024 16B-chunks
            int q = tid + 256 * i;
            int row = q >> 3, c = q & 7;
            CP_ASYNC16(sB + (row * PAF + c * 4) * 4, gb + (size_t)row * HDIM + c * 4);
        }
        CP_COMMIT();
    };

    float acc[4][4][4];
#pragma unroll
    for (int mt = 0; mt < 4; mt++)
#pragma unroll
        for (int nt = 0; nt < 4; nt++)
#pragma unroll
            for (int e = 0; e < 4; e++) acc[mt][nt][e] = 0.0f;

    // prologue: stages 0..NSTAGE-2
#pragma unroll
    for (int p = 0; p < NSTAGE - 1; p++) load_stage(p, p);

    for (int kt = 0; kt < KTILES; kt++) {
        CP_WAIT(NSTAGE - 2);
        __syncthreads();
        const int L = kt + NSTAGE - 1;
        if (L < KTILES) load_stage(L % NSTAGE, L);

        const float* As = smem + (kt % NSTAGE) * STG_FLOATS;
        const float* Bs = As + A_STG_FLOATS;
#pragma unroll
        for (int ks = 0; ks < 4; ks++) {
            const int kb = ks * 8;
            uint32_t af[4][4], bf[4][2];
#pragma unroll
            for (int mt = 0; mt < 4; mt++) {
                const float* ap = As + (warpM + 16 * mt + gid) * PAF + kb + t4;
                af[mt][0] = __float_as_uint(ap[0]);
                af[mt][1] = __float_as_uint(ap[8 * PAF]);
                af[mt][2] = __float_as_uint(ap[4]);
                af[mt][3] = __float_as_uint(ap[8 * PAF + 4]);
            }
#pragma unroll
            for (int nt = 0; nt < 4; nt++) {
                const float* bp = Bs + (warpN + 8 * nt + gid) * PAF + kb + t4;
                bf[nt][0] = __float_as_uint(bp[0]);
                bf[nt][1] = __float_as_uint(bp[4]);
            }
#pragma unroll
            for (int mt = 0; mt < 4; mt++)
#pragma unroll
                for (int nt = 0; nt < 4; nt++)
                    mma_tf32(acc[mt][nt][0], acc[mt][nt][1], acc[mt][nt][2], acc[mt][nt][3],
                             af[mt][0], af[mt][1], af[mt][2], af[mt][3],
                             bf[nt][0], bf[nt][1]);
        }
        __syncthreads();
    }
    CP_WAIT_ALL();

    // epilogue
#pragma unroll
    for (int mt = 0; mt < 4; mt++) {
#pragma unroll
        for (int nt = 0; nt < 4; nt++) {
            float v0 = acc[mt][nt][0], v1 = acc[mt][nt][1];
            float v2 = acc[mt][nt][2], v3 = acc[mt][nt][3];
            if (mode == 1) {
                v0 = 1.0f / (1.0f + __expf(-v0));
                v1 = 1.0f / (1.0f + __expf(-v1));
                v2 = 1.0f / (1.0f + __expf(-v2));
                v3 = 1.0f / (1.0f + __expf(-v3));
            }
            int row = mtB + warpM + 16 * mt + gid;
            int col = ntB + warpN + 8 * nt + 2 * t4;
            float2* p0 = (float2*)(D + (size_t)row * HDIM + col);
            float2* p1 = (float2*)(D + (size_t)(row + 8) * HDIM + col);
            *p0 = make_float2(v0, v1);
            *p1 = make_float2(v2, v3);
        }
    }
}

// ---------------- kernel: WKV elementwise ----------------
__global__ void wkv_kernel(const float4* __restrict__ aa, const float4* __restrict__ bb,
                           const float4* __restrict__ pp, const float4* __restrict__ td,
                           const float4* __restrict__ tf, float4* __restrict__ out_aa,
                           float4* __restrict__ out_bb, float4* __restrict__ out_qq) {
    int i = blockIdx.x * 256 + threadIdx.x;
    int c = i & (HDIM / 4 - 1);
    float4 k4 = g_k[i], v4 = g_v[i], r4 = g_r[i];
    float4 a4 = aa[i], b4 = bb[i], p4 = pp[i];
    float4 tf4 = tf[c], td4 = td[c];
    float kk[4] = {k4.x, k4.y, k4.z, k4.w};
    float vv[4] = {v4.x, v4.y, v4.z, v4.w};
    float rr[4] = {r4.x, r4.y, r4.z, r4.w};
    float av[4] = {a4.x, a4.y, a4.z, a4.w};
    float bv[4] = {b4.x, b4.y, b4.z, b4.w};
    float pv[4] = {p4.x, p4.y, p4.z, p4.w};
    float tfv[4] = {tf4.x, tf4.y, tf4.z, tf4.w};
    float tdv[4] = {td4.x, td4.y, td4.z, td4.w};
    float o_rw[4], o_na[4], o_nb[4], o_q2[4];
#pragma unroll
    for (int j = 0; j < 4; j++) {
        float ww = tfv[j] + kk[j];
        float qq = fmaxf(pv[j], ww);
        float e1 = __expf(pv[j] - qq);
        float e2 = __expf(ww - qq);
        float wkv = (e1 * av[j] + e2 * vv[j]) / (e1 * bv[j] + e2);
        float ww2 = pv[j] + tdv[j];
        float qq2 = fmaxf(ww2, kk[j]);
        float e1b = __expf(ww2 - qq2);
        float e2b = __expf(kk[j] - qq2);
        o_na[j] = e1b * av[j] + e2b * vv[j];
        o_nb[j] = e1b * bv[j] + e2b;
        o_q2[j] = qq2;
        o_rw[j] = tf32r(rr[j] * wkv);
    }
    float4 rw = make_float4(o_rw[0], o_rw[1], o_rw[2], o_rw[3]);
    float4 na = make_float4(o_na[0], o_na[1], o_na[2], o_na[3]);
    float4 nb = make_float4(o_nb[0], o_nb[1], o_nb[2], o_nb[3]);
    float4 q2 = make_float4(o_q2[0], o_q2[1], o_q2[2], o_q2[3]);
    g_xk[i] = rw;      // reuse as O-GEMM input
    out_aa[i] = na;
    out_bb[i] = nb;
    out_qq[i] = q2;
}

// ---------------- launch ----------------
extern "C" void kernel_launch(void* const* d_in, const int* in_sizes, int n_in,
                              void* d_out, int out_size) {
    (void)in_sizes; (void)n_in; (void)out_size;
    const float4* x   = (const float4*)d_in[0];
    const float4* al  = (const float4*)d_in[1];
    const float4* aa  = (const float4*)d_in[2];
    const float4* bb  = (const float4*)d_in[3];
    const float4* pp  = (const float4*)d_in[4];
    const float4* td  = (const float4*)d_in[5];
    const float4* tf  = (const float4*)d_in[6];
    const float4* tmk = (const float4*)d_in[7];
    const float4* tmv = (const float4*)d_in[8];
    const float4* tmr = (const float4*)d_in[9];
    const float4* Wk  = (const float4*)d_in[10];
    const float4* Wv  = (const float4*)d_in[11];
    const float4* Wr  = (const float4*)d_in[12];
    const float4* Wo  = (const float4*)d_in[13];
    float* out = (float*)d_out;

    cudaFuncSetAttribute(gemm_kernel, cudaFuncAttributeMaxDynamicSharedMemorySize, GEMM_SMEM);

    float *p_xk, *p_xv, *p_xr, *p_k, *p_v, *p_r, *p_wk, *p_wv, *p_wr, *p_wo;
    cudaGetSymbolAddress((void**)&p_xk, g_xk);
    cudaGetSymbolAddress((void**)&p_xv, g_xv);
    cudaGetSymbolAddress((void**)&p_xr, g_xr);
    cudaGetSymbolAddress((void**)&p_k,  g_k);
    cudaGetSymbolAddress((void**)&p_v,  g_v);
    cudaGetSymbolAddress((void**)&p_r,  g_r);
    cudaGetSymbolAddress((void**)&p_wk, g_wk);
    cudaGetSymbolAddress((void**)&p_wv, g_wv);
    cudaGetSymbolAddress((void**)&p_wr, g_wr);
    cudaGetSymbolAddress((void**)&p_wo, g_wo);

    wconv_kernel<<<dim3(HDIM * HDIM / 4 / 256, 4), 256>>>(Wk, Wv, Wr, Wo);
    premix_kernel<<<BHTOT / 4 / 256, 256>>>(x, al, tmk, tmv, tmr,
                                            (float4*)(out + (size_t)BHTOT));
    gemm_kernel<<<1024, 256, GEMM_SMEM>>>(p_xk, p_wk, p_k, 0);
    gemm_kernel<<<1024, 256, GEMM_SMEM>>>(p_xv, p_wv, p_v, 0);
    gemm_kernel<<<1024, 256, GEMM_SMEM>>>(p_xr, p_wr, p_r, 1);
    wkv_kernel<<<BHTOT / 4 / 256, 256>>>(aa, bb, pp, td, tf,
                                         (float4*)(out + 2 * (size_t)BHTOT),
                                         (float4*)(out + 3 * (size_t)BHTOT),
                                         (float4*)(out + 4 * (size_t)BHTOT));
    gemm_kernel<<<1024, 256, GEMM_SMEM>>>(p_xk, p_wo, out, 0);
}